// round 14
// baseline (speedup 1.0000x reference)
#include <cuda_runtime.h>
#include <cuda_fp16.h>
#include <math.h>
#include <stdint.h>

// ---------------- problem constants ----------------
#define TT 256
#define BB 256
#define FF 128
#define HH 1024

// ---------------- tiling ----------------
#define KCH     64                         // K halves per chunk
#define ROWB    144                        // 72 halves per row
#define A_BYTES (64 * ROWB)                // 9216
#define W_BYTES (128 * ROWB)               // 18432
#define STAGE_BYTES (A_BYTES + W_BYTES)    // 27648
#define SMEM_BYTES  (4 * STAGE_BYTES)      // 110592

// ---------------- persistent device state ----------------
__device__ __half g_h0h[3][BB * HH];       // triple-buffered h0
__device__ __half g_h1h[2][BB * HH];
__device__ __half g_xh[TT * BB * FF];
__device__ __half g_Wih0h[4 * HH * FF];
__device__ __half g_Whh0h[4 * HH * HH];
__device__ __half g_Wih1h[4 * HH * HH];
__device__ __half g_Whh1h[4 * HH * HH];
__device__ float  g_h0fin[BB * HH];
__device__ float  g_h1fin[BB * HH];
__device__ float  g_c0fin[BB * HH];
__device__ float  g_c1fin[BB * HH];
__device__ float  g_h1first[BB * HH];
__device__ uint32_t g_flag0[TT * 4];   // layer0 step done (per m group)
__device__ uint32_t g_flag1[TT * 4];   // layer1 step done
__device__ uint32_t g_cons[TT * 4];    // layer1 consumed h0(s+1)

// ---------------- helpers ----------------
__device__ __forceinline__ uint32_t s2u(const void* p) {
    uint32_t a;
    asm("{ .reg .u64 t; cvta.to.shared.u64 t, %1; cvt.u32.u64 %0, t; }"
        : "=r"(a) : "l"(p));
    return a;
}

__device__ __forceinline__ void cp16(uint32_t s, const void* g) {
    asm volatile("cp.async.cg.shared.global [%0], [%1], 16;" :: "r"(s), "l"(g));
}
#define CP_COMMIT() asm volatile("cp.async.commit_group;" ::: "memory")
#define CP_WAIT(N)  asm volatile("cp.async.wait_group %0;" :: "n"(N) : "memory")

__device__ __forceinline__ void ldsm4(uint32_t* r, uint32_t addr) {
    asm volatile("ldmatrix.sync.aligned.m8n8.x4.shared.b16 {%0,%1,%2,%3}, [%4];"
        : "=r"(r[0]), "=r"(r[1]), "=r"(r[2]), "=r"(r[3]) : "r"(addr));
}

__device__ __forceinline__ void mma16(float* c, const uint32_t* a, uint32_t b0, uint32_t b1) {
    asm volatile(
        "mma.sync.aligned.m16n8k16.row.col.f32.f16.f16.f32 "
        "{%0,%1,%2,%3}, {%4,%5,%6,%7}, {%8,%9}, {%0,%1,%2,%3};"
        : "+f"(c[0]), "+f"(c[1]), "+f"(c[2]), "+f"(c[3])
        : "r"(a[0]), "r"(a[1]), "r"(a[2]), "r"(a[3]), "r"(b0), "r"(b1));
}

__device__ __forceinline__ void spin_ge(const uint32_t* p, uint32_t tgt) {
    uint32_t v;
    while (true) {
        asm volatile("ld.acquire.gpu.global.u32 %0, [%1];" : "=r"(v) : "l"(p) : "memory");
        if (v >= tgt) break;
        __nanosleep(32);
    }
}

__device__ __forceinline__ void rel_add(uint32_t* p) {
    asm volatile("red.release.gpu.global.add.u32 [%0], 1;" :: "l"(p) : "memory");
}

__device__ __forceinline__ float sigmoidf_(float x) { return 1.0f / (1.0f + expf(-x)); }

// ---------------- one-shot prep: fp16 conversions + state/flag zeroing ----------------
#define N_X   (TT * BB * FF)
#define N_WI0 (4 * HH * FF)
#define N_WHH (4 * HH * HH)
#define N_Z   (BB * HH)
#define PREP_TOTAL (N_X + N_WI0 + 3 * N_WHH + 2 * N_Z + 3 * TT * 4)

__global__ void prep_all(const float* __restrict__ x,
                         const float* __restrict__ wi0, const float* __restrict__ wh0,
                         const float* __restrict__ wi1, const float* __restrict__ wh1) {
    long long i = (long long)blockIdx.x * blockDim.x + threadIdx.x;
    if (i >= PREP_TOTAL) return;
    if (i < N_X) { g_xh[i] = __float2half_rn(x[i]); return; }
    i -= N_X;
    if (i < N_WI0) { g_Wih0h[i] = __float2half_rn(wi0[i]); return; }
    i -= N_WI0;
    if (i < N_WHH) { g_Whh0h[i] = __float2half_rn(wh0[i]); return; }
    i -= N_WHH;
    if (i < N_WHH) { g_Wih1h[i] = __float2half_rn(wi1[i]); return; }
    i -= N_WHH;
    if (i < N_WHH) { g_Whh1h[i] = __float2half_rn(wh1[i]); return; }
    i -= N_WHH;
    if (i < N_Z) { g_h0h[0][i] = __float2half(0.0f); return; }
    i -= N_Z;
    if (i < N_Z) { g_h1h[0][i] = __float2half(0.0f); return; }
    i -= N_Z;
    if (i < TT * 4)     { g_flag0[i] = 0; return; }
    i -= TT * 4;
    if (i < TT * 4)     { g_flag1[i] = 0; return; }
    i -= TT * 4;
    g_cons[i] = 0;
}

// ---------------- split chunk loaders (256 threads) ----------------
__device__ __forceinline__ void loadA(uint32_t dstA, int tid,
                                      const __half* __restrict__ aSrc, int ald) {
#pragma unroll
    for (int i = 0; i < 2; i++) {            // 64 rows x 8 segs
        int q = tid + i * 256;
        int row = q >> 3, seg = q & 7;
        cp16(dstA + row * ROWB + seg * 16, aSrc + (size_t)row * ald + seg * 8);
    }
}

__device__ __forceinline__ void loadW(uint32_t dstW, int tid,
                                      const __half* __restrict__ wSrc, int wld, int j0) {
#pragma unroll
    for (int i = 0; i < 4; i++) {            // 128 rows x 8 segs
        int q = tid + i * 256;
        int row = q >> 3, seg = q & 7;
        int g = row >> 5, u = row & 31;
        cp16(dstW + row * ROWB + seg * 16,
             wSrc + (size_t)(g * HH + j0 + u) * wld + seg * 8);
    }
}

// ---------------- persistent per-CTA loop (R8 structure, locked) ----------------
// bid 0..127: m = bid&3 (batch 64-tile), nt = bid>>2 (32-unit tile).
// 8 warps = 2(m) x 4(n); warp wn covers units [8wn,8wn+8) for ALL 4 gates so
// the cell update is thread-local and c stays in registers across all steps.
template <int K_IN, int LAYER>
__device__ __forceinline__ void lstm_run(int bid, char* smraw, float* bias_s,
                                         const float* __restrict__ b_ih,
                                         const float* __restrict__ b_hh) {
    constexpr int NC    = (K_IN + HH) / KCH;     // 32 (L1) / 18 (L0)
    constexpr int SPLIT = K_IN / KCH;            // 16 (L1) / 2  (L0)

    const int tid  = threadIdx.x;
    const int w    = tid >> 5;
    const int lane = tid & 31;
    const int wm   = w & 1;
    const int wn   = w >> 1;
    const int r4   = lane >> 2, cl = lane & 3;
    const int m    = bid & 3;
    const int nt   = bid >> 2;
    const int b0   = m * 64;
    const int j0   = nt * 32;

    const uint32_t smb = s2u(smraw);
    const __half* Wih = LAYER ? g_Wih1h : g_Wih0h;
    const __half* Whh = LAYER ? g_Whh1h : g_Whh0h;

    if (tid < 128) {
        int g = tid >> 5, u = tid & 31;
        bias_s[tid] = b_ih[g * HH + j0 + u] + b_hh[g * HH + j0 + u];
    }
    __syncthreads();

    // fragment smem offsets (within a stage buffer)
    const int arow = (lane & 7) + ((lane >> 3) & 1) * 8;
    const int aseg = (lane >> 4) & 1;
    const uint32_t aoff0 = (uint32_t)((wm * 32 + arow) * ROWB + aseg * 16);
    const uint32_t aoff1 = (uint32_t)((wm * 32 + 16 + arow) * ROWB + aseg * 16);
    const uint32_t boffA = (uint32_t)((((lane >> 4) & 1) * 32 + wn * 8 + (lane & 7)) * ROWB
                                      + ((lane >> 3) & 1) * 16);
    const uint32_t boffB = boffA + 64u * ROWB;

    float c_reg[2][2][2];
#pragma unroll
    for (int a = 0; a < 2; a++)
#pragma unroll
        for (int b = 0; b < 2; b++)
#pragma unroll
            for (int d = 0; d < 2; d++) c_reg[a][b][d] = 0.0f;

#pragma unroll 1
    for (int s = 0; s < TT; s++) {
        const __half* inP = LAYER ? g_h0h[(s + 1) % 3]
                                  : g_xh + (size_t)s * BB * FF;
        const __half* hP  = LAYER ? g_h1h[s & 1] : g_h0h[s % 3];

        auto wsrc_for = [&](int ch, const __half*& ws, int& wld) {
            if (ch < SPLIT) { ws = Wih + ch * KCH; wld = K_IN; }
            else            { ws = Whh + (ch - SPLIT) * KCH; wld = HH; }
        };
        auto asrc_for = [&](int ch, const __half*& as, int& ald) {
            if (ch < SPLIT) { as = inP + (size_t)b0 * K_IN + ch * KCH; ald = K_IN; }
            else            { as = hP + (size_t)b0 * HH + (ch - SPLIT) * KCH; ald = HH; }
        };

        // ---- prologue: issue flag-independent W (and x) loads BEFORE spins ----
#pragma unroll
        for (int st = 0; st < 3; st++) {
            const __half* ws; int wld;
            wsrc_for(st, ws, wld);
            loadW(smb + st * STAGE_BYTES + A_BYTES, tid, ws, wld, j0);
        }

        if (LAYER == 0) {
            // x chunks (0,1) are always ready — issue before the h0(s) gate
            const __half* as; int ald;
            asrc_for(0, as, ald);
            loadA(smb + 0 * STAGE_BYTES, tid, as, ald);
            CP_COMMIT();                                   // group0 = {W0,W1,W2,A0}
            asrc_for(1, as, ald);
            loadA(smb + 1 * STAGE_BYTES, tid, as, ald);
            CP_COMMIT();                                   // group1 = {A1}
            if (s > 0) {
                if (tid == 0) spin_ge(&g_flag0[(s - 1) * 4 + m], 32);
                __syncthreads();
            }
            asrc_for(2, as, ald);                          // h0(s) chunk
            loadA(smb + 2 * STAGE_BYTES, tid, as, ald);
            CP_COMMIT();                                   // group2 = {A2}
        } else {
            // layer1: h0(s+1) must be complete before the A loads
            if (tid == 0) spin_ge(&g_flag0[s * 4 + m], 32);
            __syncthreads();
#pragma unroll
            for (int st = 0; st < 3; st++) {
                const __half* as; int ald;
                asrc_for(st, as, ald);
                loadA(smb + st * STAGE_BYTES, tid, as, ald);
                CP_COMMIT();
            }
        }

        float acc[2][4][4];
#pragma unroll
        for (int mi = 0; mi < 2; mi++)
#pragma unroll
            for (int g = 0; g < 4; g++)
#pragma unroll
                for (int q = 0; q < 4; q++) acc[mi][g][q] = 0.0f;

#pragma unroll 1
        for (int ch = 0; ch < NC; ch++) {
            if (ch >= NC - 1)      { CP_WAIT(0); }
            else if (ch == NC - 2) { CP_WAIT(1); }
            else                   { CP_WAIT(2); }
            __syncthreads();

            if (ch + 3 < NC) {
                int buf = (ch + 3) & 3;
                // W first — no flag dependency, overlaps the spin below
                const __half* ws; int wld;
                wsrc_for(ch + 3, ws, wld);
                loadW(smb + buf * STAGE_BYTES + A_BYTES, tid, ws, wld, j0);

                // layer1: gate h1(s) reads just before the first h1 chunk's A load
                if (LAYER == 1 && s > 0 && ch == SPLIT - 3) {
                    if (tid == 0) spin_ge(&g_flag1[(s - 1) * 4 + m], 32);
                    __syncthreads();
                }

                const __half* as; int ald;
                asrc_for(ch + 3, as, ald);
                loadA(smb + buf * STAGE_BYTES, tid, as, ald);
                CP_COMMIT();
            }

            const uint32_t aBase = smb + (ch & 3) * STAGE_BYTES;
            const uint32_t wBase = aBase + A_BYTES;

#pragma unroll
            for (int ks = 0; ks < 4; ks++) {
                uint32_t a0[4], a1[4], bA[4], bB[4];
                ldsm4(a0, aBase + aoff0 + ks * 32);
                ldsm4(a1, aBase + aoff1 + ks * 32);
                ldsm4(bA, wBase + boffA + ks * 32);
                ldsm4(bB, wBase + boffB + ks * 32);
                mma16(acc[0][0], a0, bA[0], bA[1]);
                mma16(acc[1][0], a1, bA[0], bA[1]);
                mma16(acc[0][1], a0, bA[2], bA[3]);
                mma16(acc[1][1], a1, bA[2], bA[3]);
                mma16(acc[0][2], a0, bB[0], bB[1]);
                mma16(acc[1][2], a1, bB[0], bB[1]);
                mma16(acc[0][3], a0, bB[2], bB[3]);
                mma16(acc[1][3], a1, bB[2], bB[3]);
            }
        }

        __syncthreads();
        // layer1: signal h0(s+1) fully consumed (all CTA's global reads landed)
        if (LAYER == 1 && tid == 0) rel_add(&g_cons[s * 4 + m]);

        // ---- epilogue: compute gates FIRST (before any WAR spin) ----
        float hv_all[2][2][2];
#pragma unroll
        for (int mi = 0; mi < 2; mi++)
#pragma unroll
            for (int rh = 0; rh < 2; rh++)
#pragma unroll
                for (int du = 0; du < 2; du++) {
                    const int q = rh * 2 + du;
                    const int ul = wn * 8 + 2 * cl + du;
                    float iv = acc[mi][0][q] + bias_s[ul];
                    float fv = acc[mi][1][q] + bias_s[32 + ul];
                    float gv = acc[mi][2][q] + bias_s[64 + ul];
                    float ov = acc[mi][3][q] + bias_s[96 + ul];
                    float cn = sigmoidf_(fv) * c_reg[mi][rh][du]
                             + sigmoidf_(iv) * tanhf(gv);
                    c_reg[mi][rh][du] = cn;
                    hv_all[mi][rh][du] = sigmoidf_(ov) * tanhf(cn);
                }

        // layer0 WAR: before overwriting h0 slot (s+1)%3 (= h0(s-2)), wait
        // until layer1 step s-3 consumed it (triple buffer -> 3 steps slack)
        if (LAYER == 0 && s >= 3) {
            if (tid == 0) spin_ge(&g_cons[(s - 3) * 4 + m], 32);
            __syncthreads();
        }

        __half* hOut = LAYER ? g_h1h[(s + 1) & 1] : g_h0h[(s + 1) % 3];
#pragma unroll
        for (int mi = 0; mi < 2; mi++)
#pragma unroll
            for (int rh = 0; rh < 2; rh++) {
                const int row = b0 + wm * 32 + mi * 16 + r4 + rh * 8;
                const int col = j0 + wn * 8 + 2 * cl;
                *(__half2*)&hOut[(size_t)row * HH + col] =
                    __floats2half2_rn(hv_all[mi][rh][0], hv_all[mi][rh][1]);
                if (LAYER == 1 && s == 0)
                    *(float2*)&g_h1first[(size_t)row * HH + col] =
                        make_float2(hv_all[mi][rh][0], hv_all[mi][rh][1]);
                if (s == TT - 1) {
                    float* hf = LAYER ? g_h1fin : g_h0fin;
                    float* cf = LAYER ? g_c1fin : g_c0fin;
                    *(float2*)&hf[(size_t)row * HH + col] =
                        make_float2(hv_all[mi][rh][0], hv_all[mi][rh][1]);
                    *(float2*)&cf[(size_t)row * HH + col] =
                        make_float2(c_reg[mi][rh][0], c_reg[mi][rh][1]);
                }
            }
        __syncthreads();
        if (tid == 0) rel_add(LAYER ? &g_flag1[s * 4 + m] : &g_flag0[s * 4 + m]);
    }
}

__global__ __launch_bounds__(256, 2) void lstm_persistent(
    const float* __restrict__ bih0, const float* __restrict__ bhh0,
    const float* __restrict__ bih1, const float* __restrict__ bhh1) {
    extern __shared__ char smraw[];
    __shared__ float bias_s[128];
    if (blockIdx.x < 128)
        lstm_run<HH, 1>(blockIdx.x, smraw, bias_s, bih1, bhh1);
    else
        lstm_run<FF, 0>(blockIdx.x - 128, smraw, bias_s, bih0, bhh0);
}

// ---------------- fused tail: y = h1first @ W_lin^T + b_lin, plus state packing ----------------
__global__ void tail_kernel(const float* __restrict__ W_lin,
                            const float* __restrict__ b_lin,
                            float* __restrict__ out) {
    const int bid = blockIdx.x;
    if (bid < 1024) {
        // pack h_n / c_n
        int i = bid * 256 + threadIdx.x;
        const int YO = BB * FF;
        out[YO + i]               = g_h0fin[i];
        out[YO + BB * HH + i]     = g_h1fin[i];
        out[YO + 2 * BB * HH + i] = g_c0fin[i];
        out[YO + 3 * BB * HH + i] = g_c1fin[i];
    } else {
        // linear head for batch row b
        __shared__ float hrow[HH];
        const int b = bid - 1024;
        for (int i = threadIdx.x; i < HH; i += blockDim.x)
            hrow[i] = g_h1first[(size_t)b * HH + i];
        __syncthreads();
        const int f = threadIdx.x;
        if (f < FF) {
            float acc = b_lin[f];
            const float* wv = &W_lin[(size_t)f * HH];
#pragma unroll 4
            for (int k = 0; k < HH; k++) acc += hrow[k] * wv[k];
            out[(size_t)b * FF + f] = acc;
        }
    }
}

extern "C" void kernel_launch(void* const* d_in, const int* in_sizes, int n_in,
                              void* d_out, int out_size) {
    (void)in_sizes; (void)n_in; (void)out_size;
    const float* x     = (const float*)d_in[0];
    const float* W_ih0 = (const float*)d_in[1];
    const float* W_hh0 = (const float*)d_in[2];
    const float* b_ih0 = (const float*)d_in[3];
    const float* b_hh0 = (const float*)d_in[4];
    const float* W_ih1 = (const float*)d_in[5];
    const float* W_hh1 = (const float*)d_in[6];
    const float* b_ih1 = (const float*)d_in[7];
    const float* b_hh1 = (const float*)d_in[8];
    const float* W_lin = (const float*)d_in[9];
    const float* b_lin = (const float*)d_in[10];
    float* out = (float*)d_out;

    cudaFuncSetAttribute(lstm_persistent,
                         cudaFuncAttributeMaxDynamicSharedMemorySize, SMEM_BYTES);

    prep_all<<<(PREP_TOTAL + 255) / 256, 256>>>(x, W_ih0, W_hh0, W_ih1, W_hh1);
    lstm_persistent<<<256, 256, SMEM_BYTES>>>(b_ih0, b_hh0, b_ih1, b_hh1);
    tail_kernel<<<1024 + BB, 256>>>(W_lin, b_lin, out);
}

// round 15
// speedup vs baseline: 1.0146x; 1.0146x over previous
#include <cuda_runtime.h>
#include <cuda_fp16.h>
#include <math.h>
#include <stdint.h>

// ---------------- problem constants ----------------
#define TT 256
#define BB 256
#define FF 128
#define HH 1024

// ---------------- tiling ----------------
#define KCH     64                         // K halves per chunk
#define ROWB    144                        // 72 halves per row
#define A_BYTES (64 * ROWB)                // 9216
#define W_BYTES (128 * ROWB)               // 18432
#define STAGE_BYTES (A_BYTES + W_BYTES)    // 27648
#define SMEM_BYTES  (4 * STAGE_BYTES)      // 110592

// ---------------- persistent device state ----------------
__device__ __half g_h0h[3][BB * HH];       // triple-buffered h0
__device__ __half g_h1h[2][BB * HH];
__device__ __half g_xh[TT * BB * FF];
__device__ __half g_Wih0h[4 * HH * FF];
__device__ __half g_Whh0h[4 * HH * HH];
__device__ __half g_Wih1h[4 * HH * HH];
__device__ __half g_Whh1h[4 * HH * HH];
__device__ float  g_h0fin[BB * HH];
__device__ float  g_h1fin[BB * HH];
__device__ float  g_c0fin[BB * HH];
__device__ float  g_c1fin[BB * HH];
__device__ float  g_h1first[BB * HH];
__device__ uint32_t g_flag0[TT * 4];   // layer0 step done (per m group)
__device__ uint32_t g_flag1[TT * 4];   // layer1 step done
__device__ uint32_t g_cons[TT * 4];    // layer1 consumed h0(s+1)

// ---------------- helpers ----------------
__device__ __forceinline__ uint32_t s2u(const void* p) {
    uint32_t a;
    asm("{ .reg .u64 t; cvta.to.shared.u64 t, %1; cvt.u32.u64 %0, t; }"
        : "=r"(a) : "l"(p));
    return a;
}

__device__ __forceinline__ void cp16(uint32_t s, const void* g) {
    asm volatile("cp.async.cg.shared.global [%0], [%1], 16;" :: "r"(s), "l"(g));
}
#define CP_COMMIT() asm volatile("cp.async.commit_group;" ::: "memory")
#define CP_WAIT(N)  asm volatile("cp.async.wait_group %0;" :: "n"(N) : "memory")

__device__ __forceinline__ void ldsm4(uint32_t* r, uint32_t addr) {
    asm volatile("ldmatrix.sync.aligned.m8n8.x4.shared.b16 {%0,%1,%2,%3}, [%4];"
        : "=r"(r[0]), "=r"(r[1]), "=r"(r[2]), "=r"(r[3]) : "r"(addr));
}

__device__ __forceinline__ void mma16(float* c, const uint32_t* a, uint32_t b0, uint32_t b1) {
    asm volatile(
        "mma.sync.aligned.m16n8k16.row.col.f32.f16.f16.f32 "
        "{%0,%1,%2,%3}, {%4,%5,%6,%7}, {%8,%9}, {%0,%1,%2,%3};"
        : "+f"(c[0]), "+f"(c[1]), "+f"(c[2]), "+f"(c[3])
        : "r"(a[0]), "r"(a[1]), "r"(a[2]), "r"(a[3]), "r"(b0), "r"(b1));
}

__device__ __forceinline__ void spin_ge(const uint32_t* p, uint32_t tgt) {
    uint32_t v;
    while (true) {
        asm volatile("ld.acquire.gpu.global.u32 %0, [%1];" : "=r"(v) : "l"(p) : "memory");
        if (v >= tgt) break;
        __nanosleep(32);
    }
}

__device__ __forceinline__ void rel_add(uint32_t* p) {
    asm volatile("red.release.gpu.global.add.u32 [%0], 1;" :: "l"(p) : "memory");
}

__device__ __forceinline__ float sigmoidf_(float x) { return 1.0f / (1.0f + expf(-x)); }

// ---------------- one-shot prep (8 elements/thread, vectorized) ----------------
#define N_X   (TT * BB * FF)
#define N_WI0 (4 * HH * FF)
#define N_WHH (4 * HH * HH)
#define N_Z   (BB * HH)
#define N_FLG (TT * 4)
#define PREP_TOTAL (N_X + N_WI0 + 3 * N_WHH + 2 * N_Z + 3 * N_FLG)
#define PREP_THREADS (PREP_TOTAL / 8)

__device__ __forceinline__ void cvt8(const float* __restrict__ s, __half* __restrict__ d) {
    float4 a = *(const float4*)s;
    float4 b = *(const float4*)(s + 4);
    __half2 h0 = __floats2half2_rn(a.x, a.y);
    __half2 h1 = __floats2half2_rn(a.z, a.w);
    __half2 h2 = __floats2half2_rn(b.x, b.y);
    __half2 h3 = __floats2half2_rn(b.z, b.w);
    uint4 o;
    o.x = *(uint32_t*)&h0; o.y = *(uint32_t*)&h1;
    o.z = *(uint32_t*)&h2; o.w = *(uint32_t*)&h3;
    *(uint4*)d = o;
}

__global__ void prep_all(const float* __restrict__ x,
                         const float* __restrict__ wi0, const float* __restrict__ wh0,
                         const float* __restrict__ wi1, const float* __restrict__ wh1) {
    long long v = ((long long)blockIdx.x * blockDim.x + threadIdx.x) * 8;
    if (v >= PREP_TOTAL) return;
    if (v < N_X) { cvt8(x + v, g_xh + v); return; }
    v -= N_X;
    if (v < N_WI0) { cvt8(wi0 + v, g_Wih0h + v); return; }
    v -= N_WI0;
    if (v < N_WHH) { cvt8(wh0 + v, g_Whh0h + v); return; }
    v -= N_WHH;
    if (v < N_WHH) { cvt8(wi1 + v, g_Wih1h + v); return; }
    v -= N_WHH;
    if (v < N_WHH) { cvt8(wh1 + v, g_Whh1h + v); return; }
    v -= N_WHH;
    const uint4 z = make_uint4(0, 0, 0, 0);
    if (v < N_Z) { *(uint4*)&g_h0h[0][v] = z; return; }
    v -= N_Z;
    if (v < N_Z) { *(uint4*)&g_h1h[0][v] = z; return; }
    v -= N_Z;
    if (v < N_FLG) { *(uint4*)&g_flag0[v] = z; *(uint4*)&g_flag0[v + 4] = z; return; }
    v -= N_FLG;
    if (v < N_FLG) { *(uint4*)&g_flag1[v] = z; *(uint4*)&g_flag1[v + 4] = z; return; }
    v -= N_FLG;
    *(uint4*)&g_cons[v] = z; *(uint4*)&g_cons[v + 4] = z;
}

// ---------------- split chunk loaders (256 threads) ----------------
__device__ __forceinline__ void loadA(uint32_t dstA, int tid,
                                      const __half* __restrict__ aSrc, int ald) {
#pragma unroll
    for (int i = 0; i < 2; i++) {            // 64 rows x 8 segs
        int q = tid + i * 256;
        int row = q >> 3, seg = q & 7;
        cp16(dstA + row * ROWB + seg * 16, aSrc + (size_t)row * ald + seg * 8);
    }
}

__device__ __forceinline__ void loadW(uint32_t dstW, int tid,
                                      const __half* __restrict__ wSrc, int wld, int j0) {
#pragma unroll
    for (int i = 0; i < 4; i++) {            // 128 rows x 8 segs
        int q = tid + i * 256;
        int row = q >> 3, seg = q & 7;
        int g = row >> 5, u = row & 31;
        cp16(dstW + row * ROWB + seg * 16,
             wSrc + (size_t)(g * HH + j0 + u) * wld + seg * 8);
    }
}

// ---------------- persistent per-CTA loop (R8 structure, locked) ----------------
// bid 0..127: m = bid&3 (batch 64-tile), nt = bid>>2 (32-unit tile).
// 8 warps = 2(m) x 4(n); warp wn covers units [8wn,8wn+8) for ALL 4 gates so
// the cell update is thread-local and c stays in registers across all steps.
template <int K_IN, int LAYER>
__device__ __forceinline__ void lstm_run(int bid, char* smraw, float* bias_s,
                                         const float* __restrict__ b_ih,
                                         const float* __restrict__ b_hh) {
    constexpr int NC    = (K_IN + HH) / KCH;     // 32 (L1) / 18 (L0)
    constexpr int SPLIT = K_IN / KCH;            // 16 (L1) / 2  (L0)

    const int tid  = threadIdx.x;
    const int w    = tid >> 5;
    const int lane = tid & 31;
    const int wm   = w & 1;
    const int wn   = w >> 1;
    const int r4   = lane >> 2, cl = lane & 3;
    const int m    = bid & 3;
    const int nt   = bid >> 2;
    const int b0   = m * 64;
    const int j0   = nt * 32;

    const uint32_t smb = s2u(smraw);
    const __half* Wih = LAYER ? g_Wih1h : g_Wih0h;
    const __half* Whh = LAYER ? g_Whh1h : g_Whh0h;

    if (tid < 128) {
        int g = tid >> 5, u = tid & 31;
        bias_s[tid] = b_ih[g * HH + j0 + u] + b_hh[g * HH + j0 + u];
    }
    __syncthreads();

    // fragment smem offsets (within a stage buffer)
    const int arow = (lane & 7) + ((lane >> 3) & 1) * 8;
    const int aseg = (lane >> 4) & 1;
    const uint32_t aoff0 = (uint32_t)((wm * 32 + arow) * ROWB + aseg * 16);
    const uint32_t aoff1 = (uint32_t)((wm * 32 + 16 + arow) * ROWB + aseg * 16);
    const uint32_t boffA = (uint32_t)((((lane >> 4) & 1) * 32 + wn * 8 + (lane & 7)) * ROWB
                                      + ((lane >> 3) & 1) * 16);
    const uint32_t boffB = boffA + 64u * ROWB;

    float c_reg[2][2][2];
#pragma unroll
    for (int a = 0; a < 2; a++)
#pragma unroll
        for (int b = 0; b < 2; b++)
#pragma unroll
            for (int d = 0; d < 2; d++) c_reg[a][b][d] = 0.0f;

#pragma unroll 1
    for (int s = 0; s < TT; s++) {
        const __half* inP = LAYER ? g_h0h[(s + 1) % 3]
                                  : g_xh + (size_t)s * BB * FF;
        const __half* hP  = LAYER ? g_h1h[s & 1] : g_h0h[s % 3];

        auto wsrc_for = [&](int ch, const __half*& ws, int& wld) {
            if (ch < SPLIT) { ws = Wih + ch * KCH; wld = K_IN; }
            else            { ws = Whh + (ch - SPLIT) * KCH; wld = HH; }
        };
        auto asrc_for = [&](int ch, const __half*& as, int& ald) {
            if (ch < SPLIT) { as = inP + (size_t)b0 * K_IN + ch * KCH; ald = K_IN; }
            else            { as = hP + (size_t)b0 * HH + (ch - SPLIT) * KCH; ald = HH; }
        };

        // ---- prologue: issue flag-independent W (and x) loads BEFORE spins ----
#pragma unroll
        for (int st = 0; st < 3; st++) {
            const __half* ws; int wld;
            wsrc_for(st, ws, wld);
            loadW(smb + st * STAGE_BYTES + A_BYTES, tid, ws, wld, j0);
        }

        if (LAYER == 0) {
            // x chunks (0,1) are always ready — issue before the h0(s) gate
            const __half* as; int ald;
            asrc_for(0, as, ald);
            loadA(smb + 0 * STAGE_BYTES, tid, as, ald);
            CP_COMMIT();                                   // group0 = {W0,W1,W2,A0}
            asrc_for(1, as, ald);
            loadA(smb + 1 * STAGE_BYTES, tid, as, ald);
            CP_COMMIT();                                   // group1 = {A1}
            if (s > 0) {
                if (tid == 0) spin_ge(&g_flag0[(s - 1) * 4 + m], 32);
                __syncthreads();
            }
            asrc_for(2, as, ald);                          // h0(s) chunk
            loadA(smb + 2 * STAGE_BYTES, tid, as, ald);
            CP_COMMIT();                                   // group2 = {A2}
        } else {
            // layer1: h0(s+1) must be complete before the A loads
            if (tid == 0) spin_ge(&g_flag0[s * 4 + m], 32);
            __syncthreads();
#pragma unroll
            for (int st = 0; st < 3; st++) {
                const __half* as; int ald;
                asrc_for(st, as, ald);
                loadA(smb + st * STAGE_BYTES, tid, as, ald);
                CP_COMMIT();
            }
        }

        float acc[2][4][4];
#pragma unroll
        for (int mi = 0; mi < 2; mi++)
#pragma unroll
            for (int g = 0; g < 4; g++)
#pragma unroll
                for (int q = 0; q < 4; q++) acc[mi][g][q] = 0.0f;

#pragma unroll 1
        for (int ch = 0; ch < NC; ch++) {
            if (ch >= NC - 1)      { CP_WAIT(0); }
            else if (ch == NC - 2) { CP_WAIT(1); }
            else                   { CP_WAIT(2); }
            __syncthreads();

            if (ch + 3 < NC) {
                int buf = (ch + 3) & 3;
                // W first — no flag dependency, overlaps the spin below
                const __half* ws; int wld;
                wsrc_for(ch + 3, ws, wld);
                loadW(smb + buf * STAGE_BYTES + A_BYTES, tid, ws, wld, j0);

                // layer1: gate h1(s) reads just before the first h1 chunk's A load
                if (LAYER == 1 && s > 0 && ch == SPLIT - 3) {
                    if (tid == 0) spin_ge(&g_flag1[(s - 1) * 4 + m], 32);
                    __syncthreads();
                }

                const __half* as; int ald;
                asrc_for(ch + 3, as, ald);
                loadA(smb + buf * STAGE_BYTES, tid, as, ald);
                CP_COMMIT();
            }

            const uint32_t aBase = smb + (ch & 3) * STAGE_BYTES;
            const uint32_t wBase = aBase + A_BYTES;

#pragma unroll
            for (int ks = 0; ks < 4; ks++) {
                uint32_t a0[4], a1[4], bA[4], bB[4];
                ldsm4(a0, aBase + aoff0 + ks * 32);
                ldsm4(a1, aBase + aoff1 + ks * 32);
                ldsm4(bA, wBase + boffA + ks * 32);
                ldsm4(bB, wBase + boffB + ks * 32);
                mma16(acc[0][0], a0, bA[0], bA[1]);
                mma16(acc[1][0], a1, bA[0], bA[1]);
                mma16(acc[0][1], a0, bA[2], bA[3]);
                mma16(acc[1][1], a1, bA[2], bA[3]);
                mma16(acc[0][2], a0, bB[0], bB[1]);
                mma16(acc[1][2], a1, bB[0], bB[1]);
                mma16(acc[0][3], a0, bB[2], bB[3]);
                mma16(acc[1][3], a1, bB[2], bB[3]);
            }
        }

        __syncthreads();
        // layer1: signal h0(s+1) fully consumed (all CTA's global reads landed)
        if (LAYER == 1 && tid == 0) rel_add(&g_cons[s * 4 + m]);

        // ---- epilogue: compute gates FIRST (before any WAR spin) ----
        float hv_all[2][2][2];
#pragma unroll
        for (int mi = 0; mi < 2; mi++)
#pragma unroll
            for (int rh = 0; rh < 2; rh++)
#pragma unroll
                for (int du = 0; du < 2; du++) {
                    const int q = rh * 2 + du;
                    const int ul = wn * 8 + 2 * cl + du;
                    float iv = acc[mi][0][q] + bias_s[ul];
                    float fv = acc[mi][1][q] + bias_s[32 + ul];
                    float gv = acc[mi][2][q] + bias_s[64 + ul];
                    float ov = acc[mi][3][q] + bias_s[96 + ul];
                    float cn = sigmoidf_(fv) * c_reg[mi][rh][du]
                             + sigmoidf_(iv) * tanhf(gv);
                    c_reg[mi][rh][du] = cn;
                    hv_all[mi][rh][du] = sigmoidf_(ov) * tanhf(cn);
                }

        // layer0 WAR: before overwriting h0 slot (s+1)%3 (= h0(s-2)), wait
        // until layer1 step s-3 consumed it (triple buffer -> 3 steps slack)
        if (LAYER == 0 && s >= 3) {
            if (tid == 0) spin_ge(&g_cons[(s - 3) * 4 + m], 32);
            __syncthreads();
        }

        __half* hOut = LAYER ? g_h1h[(s + 1) & 1] : g_h0h[(s + 1) % 3];
#pragma unroll
        for (int mi = 0; mi < 2; mi++)
#pragma unroll
            for (int rh = 0; rh < 2; rh++) {
                const int row = b0 + wm * 32 + mi * 16 + r4 + rh * 8;
                const int col = j0 + wn * 8 + 2 * cl;
                *(__half2*)&hOut[(size_t)row * HH + col] =
                    __floats2half2_rn(hv_all[mi][rh][0], hv_all[mi][rh][1]);
                if (LAYER == 1 && s == 0)
                    *(float2*)&g_h1first[(size_t)row * HH + col] =
                        make_float2(hv_all[mi][rh][0], hv_all[mi][rh][1]);
                if (s == TT - 1) {
                    float* hf = LAYER ? g_h1fin : g_h0fin;
                    float* cf = LAYER ? g_c1fin : g_c0fin;
                    *(float2*)&hf[(size_t)row * HH + col] =
                        make_float2(hv_all[mi][rh][0], hv_all[mi][rh][1]);
                    *(float2*)&cf[(size_t)row * HH + col] =
                        make_float2(c_reg[mi][rh][0], c_reg[mi][rh][1]);
                }
            }
        __syncthreads();
        if (tid == 0) rel_add(LAYER ? &g_flag1[s * 4 + m] : &g_flag0[s * 4 + m]);
    }
}

__global__ __launch_bounds__(256, 2) void lstm_persistent(
    const float* __restrict__ bih0, const float* __restrict__ bhh0,
    const float* __restrict__ bih1, const float* __restrict__ bhh1) {
    extern __shared__ char smraw[];
    __shared__ float bias_s[128];
    if (blockIdx.x < 128)
        lstm_run<HH, 1>(blockIdx.x, smraw, bias_s, bih1, bhh1);
    else
        lstm_run<FF, 0>(blockIdx.x - 128, smraw, bias_s, bih0, bhh0);
}

// ---------------- fused tail: y = h1first @ W_lin^T + b_lin, plus state packing ----------------
__global__ void tail_kernel(const float* __restrict__ W_lin,
                            const float* __restrict__ b_lin,
                            float* __restrict__ out) {
    const int bid = blockIdx.x;
    if (bid < 1024) {
        // pack h_n / c_n
        int i = bid * 256 + threadIdx.x;
        const int YO = BB * FF;
        out[YO + i]               = g_h0fin[i];
        out[YO + BB * HH + i]     = g_h1fin[i];
        out[YO + 2 * BB * HH + i] = g_c0fin[i];
        out[YO + 3 * BB * HH + i] = g_c1fin[i];
    } else {
        // linear head for batch row b
        __shared__ float hrow[HH];
        const int b = bid - 1024;
        for (int i = threadIdx.x; i < HH; i += blockDim.x)
            hrow[i] = g_h1first[(size_t)b * HH + i];
        __syncthreads();
        const int f = threadIdx.x;
        if (f < FF) {
            float acc = b_lin[f];
            const float* wv = &W_lin[(size_t)f * HH];
#pragma unroll 4
            for (int k = 0; k < HH; k++) acc += hrow[k] * wv[k];
            out[(size_t)b * FF + f] = acc;
        }
    }
}

extern "C" void kernel_launch(void* const* d_in, const int* in_sizes, int n_in,
                              void* d_out, int out_size) {
    (void)in_sizes; (void)n_in; (void)out_size;
    const float* x     = (const float*)d_in[0];
    const float* W_ih0 = (const float*)d_in[1];
    const float* W_hh0 = (const float*)d_in[2];
    const float* b_ih0 = (const float*)d_in[3];
    const float* b_hh0 = (const float*)d_in[4];
    const float* W_ih1 = (const float*)d_in[5];
    const float* W_hh1 = (const float*)d_in[6];
    const float* b_ih1 = (const float*)d_in[7];
    const float* b_hh1 = (const float*)d_in[8];
    const float* W_lin = (const float*)d_in[9];
    const float* b_lin = (const float*)d_in[10];
    float* out = (float*)d_out;

    cudaFuncSetAttribute(lstm_persistent,
                         cudaFuncAttributeMaxDynamicSharedMemorySize, SMEM_BYTES);

    prep_all<<<(PREP_THREADS + 255) / 256, 256>>>(x, W_ih0, W_hh0, W_ih1, W_hh1);
    lstm_persistent<<<256, 256, SMEM_BYTES>>>(b_ih0, b_hh0, b_ih1, b_hh1);
    tail_kernel<<<1024 + BB, 256>>>(W_lin, b_lin, out);
}